// round 12
// baseline (speedup 1.0000x reference)
#include <cuda_runtime.h>
#include <cstdint>

#define NROWS (256 * 32 * 32)   // 262144
#define D 64
#define K 1024
#define ESC (0.05f / 127.0f)    // global codebook quant scale (|e| < 0.05)
#define GAP_RESCUE 0.055f       // ~11 sigma of pairwise coarse noise (per-row x scale)
#define CLUSTER    0.04f        // top-4 spread below this -> warp-coop exact full scan
#define SMEM_COARSE (K * 64 + K * 4)   // int8 codebook (64KB) + b_k (4KB)

__device__ float  g_embT[K * D];   // code-major codebook [k][d] fp32 (rescue/gather)
__device__ float  g_sqe[K];        // ||e_k||^2 exact fp32
__device__ int4   g_E8[K * 4];     // int8 codebook (global scale ESC), 4 x int4 per code
__device__ float  g_B[K];          // b_k = sqe_k + 8 (keeps coarse score positive)
__device__ uint4  g_cand[NROWS];   // coarse top-4 sortable keys per row (ascending)
__device__ double g_acc;

// ---------------- helpers ----------------
__device__ __forceinline__ int pack4(int a, int b, int c, int d) {
    return (int)((unsigned)(a & 0xff) | ((unsigned)(b & 0xff) << 8) |
                 ((unsigned)(c & 0xff) << 16) | ((unsigned)(d & 0xff) << 24));
}
__device__ __forceinline__ int q8s(float v, float inv) {
    return max(-127, min(127, __float2int_rn(v * inv)));
}

// H1 bit-exact emulation of the reference arithmetic (identical to passing R7/R9 path)
__device__ __forceinline__ int h1_emulate(const float* xv, int lo, int hi) {
    float l0 = 0.f, l1 = 0.f, l2 = 0.f, l3 = 0.f;
    #pragma unroll 4
    for (int d = 0; d < 64; d += 4) {
        l0 = fmaf(xv[d],     xv[d],     l0);
        l1 = fmaf(xv[d + 1], xv[d + 1], l1);
        l2 = fmaf(xv[d + 2], xv[d + 2], l2);
        l3 = fmaf(xv[d + 3], xv[d + 3], l3);
    }
    float A = (l0 + l1) + (l2 + l3);
    float Bl = 0.f, Bh = 0.f, dl = 0.f, dh = 0.f;
    #pragma unroll 8
    for (int d = 0; d < 64; d++) {
        float el = g_embT[lo * D + d], eh = g_embT[hi * D + d];
        Bl = fmaf(el, el, Bl);
        Bh = fmaf(eh, eh, Bh);
        dl = fmaf(xv[d], el, dl);
        dh = fmaf(xv[d], eh, dh);
    }
    float distlo = (A + Bl) - 2.0f * dl;
    float disthi = (A + Bh) - 2.0f * dh;
    return (disthi < distlo) ? hi : lo;   // strict '<': ties -> lower index
}

// ---------------- init ----------------
__global__ void vq_init_kernel(const float* __restrict__ emb) {
    int i = blockIdx.x * blockDim.x + threadIdx.x;   // 65536 threads
    if (i == 0) g_acc = 0.0;
    if (i < K * D) {
        int d = i >> 10;            // emb is [d][k]
        int k = i & (K - 1);
        g_embT[k * D + d] = emb[i];
    }
    if (i < K) {
        float s = 0.f;
        #pragma unroll 8
        for (int d = 0; d < D; d++) {
            float v = emb[d * K + i];
            s = fmaf(v, v, s);
        }
        g_sqe[i] = s;
        g_B[i] = s + 8.0f;
        float inv = 1.0f / ESC;
        int w[16];
        #pragma unroll 4
        for (int j = 0; j < 16; j++) {
            w[j] = pack4(q8s(emb[(4 * j)     * K + i], inv), q8s(emb[(4 * j + 1) * K + i], inv),
                         q8s(emb[(4 * j + 2) * K + i], inv), q8s(emb[(4 * j + 3) * K + i], inv));
        }
        #pragma unroll
        for (int j = 0; j < 4; j++)
            g_E8[i * 4 + j] = make_int4(w[4 * j], w[4 * j + 1], w[4 * j + 2], w[4 * j + 3]);
    }
}

// ---------------- coarse: dp4a int8 (per-row x scale), branchless top-4 keys ----------------
__global__ void __launch_bounds__(256) vq_coarse(const float* __restrict__ x) {
    extern __shared__ char smem[];
    int4*  sE = (int4*)smem;                 // [K*4]
    float* sB = (float*)(smem + K * 64);     // [K]
    int tid = threadIdx.x;

    for (int j = tid; j < K * 4; j += 256) sE[j] = g_E8[j];
    for (int j = tid; j < K; j += 256)     sB[j] = g_B[j];

    // per-row max and quantization
    int row = blockIdx.x * 256 + tid;
    const float4* xp = (const float4*)(x + (size_t)row * D);
    float4 vv[16];
    float mx = 1e-6f;
    #pragma unroll
    for (int i = 0; i < 16; i++) {
        vv[i] = xp[i];
        mx = fmaxf(mx, fmaxf(fmaxf(fabsf(vv[i].x), fabsf(vv[i].y)),
                             fmaxf(fabsf(vv[i].z), fabsf(vv[i].w))));
    }
    float inv = 127.0f / mx;
    int xq[16];
    #pragma unroll
    for (int i = 0; i < 16; i++)
        xq[i] = pack4(__float2int_rn(vv[i].x * inv), __float2int_rn(vv[i].y * inv),
                      __float2int_rn(vv[i].z * inv), __float2int_rn(vv[i].w * inv));
    float m_row = -2.0f * (mx / 127.0f) * ESC;
    __syncthreads();

    unsigned k0 = 0xFFFFFFFFu, k1 = 0xFFFFFFFFu, k2 = 0xFFFFFFFFu, k3 = 0xFFFFFFFFu;
    #pragma unroll 2
    for (int k = 0; k < K; k++) {
        int4 e0 = sE[4 * k], e1 = sE[4 * k + 1], e2 = sE[4 * k + 2], e3 = sE[4 * k + 3];
        int a = 0, b = 0;
        a = __dp4a(xq[0],  e0.x, a);  b = __dp4a(xq[8],  e2.x, b);
        a = __dp4a(xq[1],  e0.y, a);  b = __dp4a(xq[9],  e2.y, b);
        a = __dp4a(xq[2],  e0.z, a);  b = __dp4a(xq[10], e2.z, b);
        a = __dp4a(xq[3],  e0.w, a);  b = __dp4a(xq[11], e2.w, b);
        a = __dp4a(xq[4],  e1.x, a);  b = __dp4a(xq[12], e3.x, b);
        a = __dp4a(xq[5],  e1.y, a);  b = __dp4a(xq[13], e3.y, b);
        a = __dp4a(xq[6],  e1.z, a);  b = __dp4a(xq[14], e3.z, b);
        a = __dp4a(xq[7],  e1.w, a);  b = __dp4a(xq[15], e3.w, b);
        float sc = fmaf((float)(a + b), m_row, sB[k]);   // positive (~6..11)
        unsigned key = (__float_as_uint(sc) & 0xFFFFFC00u) | (unsigned)k;
        // sorted insertion into (k0<=k1<=k2<=k3)
        unsigned t = key, m;
        m = min(k0, t); t = max(k0, t); k0 = m;
        m = min(k1, t); t = max(k1, t); k1 = m;
        m = min(k2, t); t = max(k2, t); k2 = m;
        k3 = min(k3, t);
    }
    g_cand[row] = make_uint4(k0, k1, k2, k3);
}

// ---------------- finish: rescue (top-4 exact / warp-coop full scan / H1) + gather + loss ----------------
__global__ void __launch_bounds__(256) vq_finish(const float* __restrict__ x,
                                                 float* __restrict__ out) {
    __shared__ int    sIdx[256];
    __shared__ double sred[8];
    int tid = threadIdx.x, lane = tid & 31;
    int row = blockIdx.x * 256 + tid;

    uint4 c = g_cand[row];
    float s0 = __uint_as_float(c.x & 0xFFFFFC00u);
    float s1 = __uint_as_float(c.y & 0xFFFFFC00u);
    float s3 = __uint_as_float(c.w & 0xFFFFFC00u);
    int id0 = (int)(c.x & 1023u);

    int widx = id0;
    bool rescue = (s1 - s0 < GAP_RESCUE);
    bool full   = rescue && (s3 - s0 < CLUSTER);

    // warp-cooperative exact full scans for clustered rows (rare)
    unsigned fmask = __ballot_sync(0xffffffffu, full);
    while (fmask) {
        int src = __ffs(fmask) - 1;
        fmask &= fmask - 1;
        int r = __shfl_sync(0xffffffffu, row, src);
        float xs[64];
        const float4* xrp = (const float4*)(x + (size_t)r * D);
        #pragma unroll
        for (int i = 0; i < 16; i++) {
            float4 v = xrp[i];   // broadcast loads
            xs[4 * i] = v.x; xs[4 * i + 1] = v.y; xs[4 * i + 2] = v.z; xs[4 * i + 3] = v.w;
        }
        float b0 = 3e38f, b1 = 3e38f;
        int i0 = 0, i1 = 0;
        for (int k = lane; k < K; k += 32) {   // ascending per lane
            const float* e = &g_embT[k * D];
            float dot = 0.f;
            #pragma unroll 8
            for (int d = 0; d < D; d++) dot = fmaf(xs[d], e[d], dot);
            float val = fmaf(dot, -2.f, g_sqe[k]);
            if (val < b0)      { b1 = b0; i1 = i0; b0 = val; i0 = k; }
            else if (val < b1) { b1 = val; i1 = k; }
        }
        // lexicographic merge (value, then lower index) across the warp
        #pragma unroll
        for (int off = 16; off; off >>= 1) {
            float ob0 = __shfl_xor_sync(0xffffffffu, b0, off);
            float ob1 = __shfl_xor_sync(0xffffffffu, b1, off);
            int   oi0 = __shfl_xor_sync(0xffffffffu, i0, off);
            int   oi1 = __shfl_xor_sync(0xffffffffu, i1, off);
            bool owin = (ob0 < b0) || (ob0 == b0 && oi0 < i0);
            if (owin) {
                float tf = b0; b0 = ob0; ob0 = tf;
                int   ti = i0; i0 = oi0; oi0 = ti;
                tf = b1; b1 = ob1; ob1 = tf;
                ti = i1; i1 = oi1; oi1 = ti;
            }
            if ((ob0 < b1) || (ob0 == b1 && oi0 < i1)) { b1 = ob0; i1 = oi0; }
        }
        if (lane == src)
            widx = (b1 - b0 < 1e-3f) ? h1_emulate(xs, min(i0, i1), max(i0, i1)) : i0;
    }

    if (rescue && !full) {
        float xv[64];
        const float4* xp = (const float4*)(x + (size_t)row * D);
        #pragma unroll
        for (int i = 0; i < 16; i++) {
            float4 v = xp[i];
            xv[4 * i] = v.x; xv[4 * i + 1] = v.y; xv[4 * i + 2] = v.z; xv[4 * i + 3] = v.w;
        }
        int ids[4] = { (int)(c.x & 1023u), (int)(c.y & 1023u),
                       (int)(c.z & 1023u), (int)(c.w & 1023u) };
        // sort ids ascending (first-index tie semantics), then strict '<' scan
        #pragma unroll
        for (int a = 1; a < 4; a++) {
            int v = ids[a], b = a;
            while (b > 0 && ids[b - 1] > v) { ids[b] = ids[b - 1]; b--; }
            ids[b] = v;
        }
        float b0 = 3e38f, b1 = 3e38f;
        int i0 = 0, i1 = 0;
        #pragma unroll
        for (int j = 0; j < 4; j++) {
            const float* e = &g_embT[ids[j] * D];
            float dot = 0.f;
            #pragma unroll 8
            for (int d = 0; d < D; d++) dot = fmaf(xv[d], e[d], dot);
            float val = fmaf(dot, -2.f, g_sqe[ids[j]]);
            if (val < b0)      { b1 = b0; i1 = i0; b0 = val; i0 = ids[j]; }
            else if (val < b1) { b1 = val; i1 = ids[j]; }
        }
        widx = (b1 - b0 < 1e-3f) ? h1_emulate(xv, min(i0, i1), max(i0, i1)) : i0;
    }
    sIdx[tid] = widx;
    __syncthreads();

    // phase B: block's 256 rows -> straight-through output + double loss accum
    size_t base = (size_t)blockIdx.x * 256 * D;
    double local = 0.0;
    #pragma unroll
    for (int it = 0; it < 16; it++) {
        int j = it * 256 + tid;          // 0..4095 float4s
        int r = j >> 4, dd = j & 15;
        int idx = sIdx[r];
        float4 qv = ((const float4*)g_embT)[idx * 16 + dd];
        float4 xv = *(const float4*)(x + base + (size_t)j * 4);
        float d0 = qv.x - xv.x, d1 = qv.y - xv.y, d2 = qv.z - xv.z, d3 = qv.w - xv.w;
        float4 o;
        o.x = xv.x + d0; o.y = xv.y + d1; o.z = xv.z + d2; o.w = xv.w + d3;
        *(float4*)(out + base + (size_t)j * 4) = o;
        local += (double)d0 * d0 + (double)d1 * d1 + (double)d2 * d2 + (double)d3 * d3;
    }
    #pragma unroll
    for (int off = 16; off > 0; off >>= 1)
        local += __shfl_down_sync(0xffffffffu, local, off);
    int w = tid >> 5, l = tid & 31;
    if (l == 0) sred[w] = local;
    __syncthreads();
    if (tid == 0) {
        double s = 0.0;
        #pragma unroll
        for (int k = 0; k < 8; k++) s += sred[k];
        atomicAdd(&g_acc, s);
    }
}

__global__ void vq_finalize_kernel(float* __restrict__ loss_out) {
    double m = g_acc / (double)((long)NROWS * D);
    float lf = (float)m;
    *loss_out = 0.25f * lf + lf;   // BETA*commitment + codebook (equal values)
}

extern "C" void kernel_launch(void* const* d_in, const int* in_sizes, int n_in,
                              void* d_out, int out_size) {
    const float* x   = (const float*)d_in[0];   // [256,32,32,64] fp32
    const float* emb = (const float*)d_in[1];   // [64,1024] fp32
    float* out = (float*)d_out;

    cudaFuncSetAttribute(vq_coarse, cudaFuncAttributeMaxDynamicSharedMemorySize, SMEM_COARSE);

    vq_init_kernel<<<256, 256>>>(emb);
    vq_coarse<<<NROWS / 256, 256, SMEM_COARSE>>>(x);
    vq_finish<<<NROWS / 256, 256>>>(x, out);
    vq_finalize_kernel<<<1, 1>>>(out + (out_size - 1));
}

// round 13
// speedup vs baseline: 1.5494x; 1.5494x over previous
#include <cuda_runtime.h>
#include <cstdint>

#define NROWS (256 * 32 * 32)   // 262144
#define D 64
#define K 1024
#define KC 128                  // codes per smem chunk
#define SROW 68                 // padded row stride (floats), 272B
#define GAP_RESCUE 2.0e-3f      // key granularity 9.8e-4 + H1 band 1e-3
#define CLUSTER    2.5e-3f      // top-4 key spread below this -> warp full scan (safety)
#define SMEM_COARSE (KC * SROW * 4 + KC * 8)

__device__ float  g_embT[K * D];   // code-major codebook [k][d] fp32
__device__ float  g_sqe[K];        // ||e_k||^2 exact fp32
__device__ float2 g_sq2[K];        // (sqe_k + 8, 0) packed accumulator seed
__device__ uint4  g_cand[NROWS];   // top-4 sortable keys per row (ascending)
__device__ double g_acc;

typedef unsigned long long ull;

__device__ __forceinline__ void ffma2(ull &c, ull a, ull b) {
    asm("fma.rn.f32x2 %0, %1, %2, %0;" : "+l"(c) : "l"(a), "l"(b));
}
__device__ __forceinline__ ull fadd2(ull a, ull b) {
    ull r;
    asm("add.rn.f32x2 %0, %1, %2;" : "=l"(r) : "l"(a), "l"(b));
    return r;
}
__device__ __forceinline__ ull fmul2(ull a, ull b) {
    ull r;
    asm("mul.rn.f32x2 %0, %1, %2;" : "=l"(r) : "l"(a), "l"(b));
    return r;
}

// H1 bit-exact emulation of the reference arithmetic (identical to passing R7/R9/R12 path)
__device__ __forceinline__ int h1_emulate(const float* xv, int lo, int hi) {
    float l0 = 0.f, l1 = 0.f, l2 = 0.f, l3 = 0.f;
    #pragma unroll 4
    for (int d = 0; d < 64; d += 4) {
        l0 = fmaf(xv[d],     xv[d],     l0);
        l1 = fmaf(xv[d + 1], xv[d + 1], l1);
        l2 = fmaf(xv[d + 2], xv[d + 2], l2);
        l3 = fmaf(xv[d + 3], xv[d + 3], l3);
    }
    float A = (l0 + l1) + (l2 + l3);
    float Bl = 0.f, Bh = 0.f, dl = 0.f, dh = 0.f;
    #pragma unroll 8
    for (int d = 0; d < 64; d++) {
        float el = g_embT[lo * D + d], eh = g_embT[hi * D + d];
        Bl = fmaf(el, el, Bl);
        Bh = fmaf(eh, eh, Bh);
        dl = fmaf(xv[d], el, dl);
        dh = fmaf(xv[d], eh, dh);
    }
    float distlo = (A + Bl) - 2.0f * dl;
    float disthi = (A + Bh) - 2.0f * dh;
    return (disthi < distlo) ? hi : lo;   // strict '<': ties -> lower index
}

// ---------------- init ----------------
__global__ void vq_init_kernel(const float* __restrict__ emb) {
    int i = blockIdx.x * blockDim.x + threadIdx.x;   // 65536 threads
    if (i == 0) g_acc = 0.0;
    if (i < K * D) {
        int d = i >> 10;            // emb is [d][k]
        int k = i & (K - 1);
        g_embT[k * D + d] = emb[i];
    }
    if (i < K) {
        float s = 0.f;
        #pragma unroll 8
        for (int d = 0; d < D; d++) {
            float v = emb[d * K + i];
            s = fmaf(v, v, s);
        }
        g_sqe[i] = s;
        g_sq2[i] = make_float2(s + 8.0f, 0.0f);
    }
}

// ---------------- coarse: exact fp32 FFMA2 scores, alu-pipe top-4 keys ----------------
// score_k = (sqe_k + 8) - 2 x.e_k, computed in clean fp32. Per-code fma-pipe cost:
// 32 FFMA2 + 1 FADD2 + 1 FADD = 34 instrs (68 cyc @ rt2). Selection rides the alu pipe.
__global__ void __launch_bounds__(256) vq_coarse(const float* __restrict__ x) {
    extern __shared__ char smem[];
    float*  sE  = (float*)smem;                        // [KC * SROW]
    float2* sQ2 = (float2*)(smem + KC * SROW * 4);     // [KC]
    int tid = threadIdx.x;
    int row = blockIdx.x * 256 + tid;

    // x row as 32 packed f32x2, pre-scaled by -2
    ull xr[32];
    {
        ull neg2;
        {
            float2 t = make_float2(-2.0f, -2.0f);
            neg2 = *(ull*)&t;
        }
        const ulonglong2* xp = (const ulonglong2*)(x + (size_t)row * D);
        #pragma unroll
        for (int i = 0; i < 16; i++) {
            ulonglong2 v = xp[i];
            xr[2 * i]     = fmul2(v.x, neg2);
            xr[2 * i + 1] = fmul2(v.y, neg2);
        }
    }

    unsigned k0 = 0xFFFFFFFFu, k1 = 0xFFFFFFFFu, k2 = 0xFFFFFFFFu, k3 = 0xFFFFFFFFu;

    for (int c0 = 0; c0 < K; c0 += KC) {
        __syncthreads();
        // coalesced chunk fill (conflict-free strided smem writes)
        #pragma unroll
        for (int i = tid; i < KC * D; i += 256) {
            int kc = i >> 6, d = i & 63;
            sE[kc * SROW + d] = g_embT[(c0 + kc) * D + d];
        }
        if (tid < KC) sQ2[tid] = g_sq2[c0 + tid];
        __syncthreads();

        #pragma unroll 2
        for (int kc = 0; kc < KC; kc++) {
            const ulonglong2* ep = (const ulonglong2*)&sE[kc * SROW];
            ull acc0 = *(const ull*)&sQ2[kc];   // (sqe+8, 0)
            ull acc1 = 0ull;
            #pragma unroll
            for (int i = 0; i < 8; i++) {
                ulonglong2 e0 = ep[2 * i];
                ulonglong2 e1 = ep[2 * i + 1];
                ffma2(acc0, xr[4 * i],     e0.x);
                ffma2(acc1, xr[4 * i + 1], e0.y);
                ffma2(acc0, xr[4 * i + 2], e1.x);
                ffma2(acc1, xr[4 * i + 3], e1.y);
            }
            ull s = fadd2(acc0, acc1);
            float val = __uint_as_float((unsigned)s) + __uint_as_float((unsigned)(s >> 32));
            // val in ~[6.5, 9.6] > 0: float bits are order-preserving
            unsigned key = (__float_as_uint(val) & 0xFFFFFC00u) | (unsigned)(c0 + kc);
            unsigned t = key, m;
            m = min(k0, t); t = max(k0, t); k0 = m;
            m = min(k1, t); t = max(k1, t); k1 = m;
            m = min(k2, t); t = max(k2, t); k2 = m;
            k3 = min(k3, t);
        }
    }
    g_cand[row] = make_uint4(k0, k1, k2, k3);
}

// ---------------- finish: rescue (top-4 exact / warp full scan / H1) + gather + loss ----------------
__global__ void __launch_bounds__(256) vq_finish(const float* __restrict__ x,
                                                 float* __restrict__ out) {
    __shared__ int    sIdx[256];
    __shared__ double sred[8];
    int tid = threadIdx.x, lane = tid & 31;
    int row = blockIdx.x * 256 + tid;

    uint4 c = g_cand[row];
    float s0 = __uint_as_float(c.x & 0xFFFFFC00u);
    float s1 = __uint_as_float(c.y & 0xFFFFFC00u);
    float s3 = __uint_as_float(c.w & 0xFFFFFC00u);
    int id0 = (int)(c.x & 1023u);

    int widx = id0;
    bool rescue = (s1 - s0 < GAP_RESCUE);
    bool full   = rescue && (s3 - s0 < CLUSTER);

    // warp-cooperative exact full scans for 4-way-clustered rows (expected ~0)
    unsigned fmask = __ballot_sync(0xffffffffu, full);
    while (fmask) {
        int src = __ffs(fmask) - 1;
        fmask &= fmask - 1;
        int r = __shfl_sync(0xffffffffu, row, src);
        float xs[64];
        const float4* xrp = (const float4*)(x + (size_t)r * D);
        #pragma unroll
        for (int i = 0; i < 16; i++) {
            float4 v = xrp[i];
            xs[4 * i] = v.x; xs[4 * i + 1] = v.y; xs[4 * i + 2] = v.z; xs[4 * i + 3] = v.w;
        }
        float b0 = 3e38f, b1 = 3e38f;
        int i0 = 0, i1 = 0;
        for (int k = lane; k < K; k += 32) {
            const float* e = &g_embT[k * D];
            float dot = 0.f;
            #pragma unroll 8
            for (int d = 0; d < D; d++) dot = fmaf(xs[d], e[d], dot);
            float val = fmaf(dot, -2.f, g_sqe[k]);
            if (val < b0)      { b1 = b0; i1 = i0; b0 = val; i0 = k; }
            else if (val < b1) { b1 = val; i1 = k; }
        }
        #pragma unroll
        for (int off = 16; off; off >>= 1) {
            float ob0 = __shfl_xor_sync(0xffffffffu, b0, off);
            float ob1 = __shfl_xor_sync(0xffffffffu, b1, off);
            int   oi0 = __shfl_xor_sync(0xffffffffu, i0, off);
            int   oi1 = __shfl_xor_sync(0xffffffffu, i1, off);
            bool owin = (ob0 < b0) || (ob0 == b0 && oi0 < i0);
            if (owin) {
                float tf = b0; b0 = ob0; ob0 = tf;
                int   ti = i0; i0 = oi0; oi0 = ti;
                tf = b1; b1 = ob1; ob1 = tf;
                ti = i1; i1 = oi1; oi1 = ti;
            }
            if ((ob0 < b1) || (ob0 == b1 && oi0 < i1)) { b1 = ob0; i1 = oi0; }
        }
        if (lane == src)
            widx = (b1 - b0 < 1e-3f) ? h1_emulate(xs, min(i0, i1), max(i0, i1)) : i0;
    }

    if (rescue && !full) {
        float xv[64];
        const float4* xp = (const float4*)(x + (size_t)row * D);
        #pragma unroll
        for (int i = 0; i < 16; i++) {
            float4 v = xp[i];
            xv[4 * i] = v.x; xv[4 * i + 1] = v.y; xv[4 * i + 2] = v.z; xv[4 * i + 3] = v.w;
        }
        int ids[4] = { (int)(c.x & 1023u), (int)(c.y & 1023u),
                       (int)(c.z & 1023u), (int)(c.w & 1023u) };
        #pragma unroll
        for (int a = 1; a < 4; a++) {
            int v = ids[a], b = a;
            while (b > 0 && ids[b - 1] > v) { ids[b] = ids[b - 1]; b--; }
            ids[b] = v;
        }
        float b0 = 3e38f, b1 = 3e38f;
        int i0 = 0, i1 = 0;
        #pragma unroll
        for (int j = 0; j < 4; j++) {
            const float* e = &g_embT[ids[j] * D];
            float dot = 0.f;
            #pragma unroll 8
            for (int d = 0; d < D; d++) dot = fmaf(xv[d], e[d], dot);
            float val = fmaf(dot, -2.f, g_sqe[ids[j]]);
            if (val < b0)      { b1 = b0; i1 = i0; b0 = val; i0 = ids[j]; }
            else if (val < b1) { b1 = val; i1 = ids[j]; }
        }
        widx = (b1 - b0 < 1e-3f) ? h1_emulate(xv, min(i0, i1), max(i0, i1)) : i0;
    }
    sIdx[tid] = widx;
    __syncthreads();

    // phase B: block's 256 rows -> straight-through output + double loss accum
    size_t base = (size_t)blockIdx.x * 256 * D;
    double local = 0.0;
    #pragma unroll
    for (int it = 0; it < 16; it++) {
        int j = it * 256 + tid;          // 0..4095 float4s
        int r = j >> 4, dd = j & 15;
        int idx = sIdx[r];
        float4 qv = ((const float4*)g_embT)[idx * 16 + dd];
        float4 xv = *(const float4*)(x + base + (size_t)j * 4);
        float d0 = qv.x - xv.x, d1 = qv.y - xv.y, d2 = qv.z - xv.z, d3 = qv.w - xv.w;
        float4 o;
        o.x = xv.x + d0; o.y = xv.y + d1; o.z = xv.z + d2; o.w = xv.w + d3;
        *(float4*)(out + base + (size_t)j * 4) = o;
        local += (double)d0 * d0 + (double)d1 * d1 + (double)d2 * d2 + (double)d3 * d3;
    }
    #pragma unroll
    for (int off = 16; off > 0; off >>= 1)
        local += __shfl_down_sync(0xffffffffu, local, off);
    int w = tid >> 5, l = tid & 31;
    if (l == 0) sred[w] = local;
    __syncthreads();
    if (tid == 0) {
        double s = 0.0;
        #pragma unroll
        for (int k = 0; k < 8; k++) s += sred[k];
        atomicAdd(&g_acc, s);
    }
}

__global__ void vq_finalize_kernel(float* __restrict__ loss_out) {
    double m = g_acc / (double)((long)NROWS * D);
    float lf = (float)m;
    *loss_out = 0.25f * lf + lf;   // BETA*commitment + codebook (equal values)
}

extern "C" void kernel_launch(void* const* d_in, const int* in_sizes, int n_in,
                              void* d_out, int out_size) {
    const float* x   = (const float*)d_in[0];   // [256,32,32,64] fp32
    const float* emb = (const float*)d_in[1];   // [64,1024] fp32
    float* out = (float*)d_out;

    cudaFuncSetAttribute(vq_coarse, cudaFuncAttributeMaxDynamicSharedMemorySize, SMEM_COARSE);

    vq_init_kernel<<<256, 256>>>(emb);
    vq_coarse<<<NROWS / 256, 256, SMEM_COARSE>>>(x);
    vq_finish<<<NROWS / 256, 256>>>(x, out);
    vq_finalize_kernel<<<1, 1>>>(out + (out_size - 1));
}

// round 14
// speedup vs baseline: 1.6997x; 1.0970x over previous
#include <cuda_runtime.h>
#include <cstdint>

#define NROWS (256 * 32 * 32)   // 262144
#define D 64
#define K 1024
#define KC 128                  // codes per smem chunk
#define SROW 68                 // padded row stride (floats), 272B
#define GAP_RESCUE 2.0e-3f      // key granularity 9.8e-4 + H1 band 1e-3
#define CLUSTER    2.5e-3f      // top-4 key spread below this -> warp full scan
#define SMEM_SZ (KC * SROW * 4 + KC * 8)

__device__ float  g_embT[K * D];   // code-major codebook [k][d] fp32
__device__ float  g_sqe[K];        // ||e_k||^2 exact fp32
__device__ float2 g_sq2[K];        // (sqe_k + 8, 0) packed accumulator seed
__device__ double g_acc;

typedef unsigned long long ull;

__device__ __forceinline__ void ffma2(ull &c, ull a, ull b) {
    asm("fma.rn.f32x2 %0, %1, %2, %0;" : "+l"(c) : "l"(a), "l"(b));
}
__device__ __forceinline__ ull fadd2(ull a, ull b) {
    ull r;
    asm("add.rn.f32x2 %0, %1, %2;" : "=l"(r) : "l"(a), "l"(b));
    return r;
}
__device__ __forceinline__ ull fmul2(ull a, ull b) {
    ull r;
    asm("mul.rn.f32x2 %0, %1, %2;" : "=l"(r) : "l"(a), "l"(b));
    return r;
}
__device__ __forceinline__ float plo(ull p) { return __uint_as_float((unsigned)p); }
__device__ __forceinline__ float phi(ull p) { return __uint_as_float((unsigned)(p >> 32)); }

// H1 bit-exact emulation of the reference arithmetic (identical decision math to the
// passing R7/R9/R12/R13 path); x read from global (cold path).
__device__ __noinline__ int h1_emulate_g(const float* __restrict__ xg, int lo, int hi) {
    float l0 = 0.f, l1 = 0.f, l2 = 0.f, l3 = 0.f;
    #pragma unroll 4
    for (int d = 0; d < 64; d += 4) {
        l0 = fmaf(xg[d],     xg[d],     l0);
        l1 = fmaf(xg[d + 1], xg[d + 1], l1);
        l2 = fmaf(xg[d + 2], xg[d + 2], l2);
        l3 = fmaf(xg[d + 3], xg[d + 3], l3);
    }
    float A = (l0 + l1) + (l2 + l3);
    float Bl = 0.f, Bh = 0.f, dl = 0.f, dh = 0.f;
    #pragma unroll 8
    for (int d = 0; d < 64; d++) {
        float el = g_embT[lo * D + d], eh = g_embT[hi * D + d];
        Bl = fmaf(el, el, Bl);
        Bh = fmaf(eh, eh, Bh);
        dl = fmaf(xg[d], el, dl);
        dh = fmaf(xg[d], eh, dh);
    }
    float distlo = (A + Bl) - 2.0f * dl;
    float disthi = (A + Bh) - 2.0f * dh;
    return (disthi < distlo) ? hi : lo;   // strict '<': ties -> lower index
}

// ---------------- init ----------------
__global__ void vq_init_kernel(const float* __restrict__ emb) {
    int i = blockIdx.x * blockDim.x + threadIdx.x;   // 65536 threads
    if (i == 0) g_acc = 0.0;
    if (i < K * D) {
        int d = i >> 10;            // emb is [d][k]
        int k = i & (K - 1);
        g_embT[k * D + d] = emb[i];
    }
    if (i < K) {
        float s = 0.f;
        #pragma unroll 8
        for (int d = 0; d < D; d++) {
            float v = emb[d * K + i];
            s = fmaf(v, v, s);
        }
        g_sqe[i] = s;
        g_sq2[i] = make_float2(s + 8.0f, 0.0f);
    }
}

// ---------------- mega: exact fp32 FFMA2 coarse + rescue + output + loss ----------------
__global__ void __launch_bounds__(256, 2) vq_mega(const float* __restrict__ x,
                                                  float* __restrict__ out) {
    extern __shared__ char smem[];
    float* sE = (float*)smem;                          // [KC * SROW]
    __shared__ double sred[8];
    int tid = threadIdx.x, lane = tid & 31;
    int row = blockIdx.x * 256 + tid;

    // x row as 32 packed f32x2, pre-scaled by -2 (exact; x recoverable as -0.5*xr)
    ull xr[32];
    {
        float2 t = make_float2(-2.0f, -2.0f);
        ull neg2 = *(ull*)&t;
        const ulonglong2* xp = (const ulonglong2*)(x + (size_t)row * D);
        #pragma unroll
        for (int i = 0; i < 16; i++) {
            ulonglong2 v = xp[i];
            xr[2 * i]     = fmul2(v.x, neg2);
            xr[2 * i + 1] = fmul2(v.y, neg2);
        }
    }

    unsigned k0 = 0xFFFFFFFFu, k1 = 0xFFFFFFFFu, k2 = 0xFFFFFFFFu, k3 = 0xFFFFFFFFu;

    for (int c0 = 0; c0 < K; c0 += KC) {
        __syncthreads();
        #pragma unroll
        for (int i = tid; i < KC * D; i += 256) {
            int kc = i >> 6, d = i & 63;
            sE[kc * SROW + d] = g_embT[(c0 + kc) * D + d];
        }
        float2* sQ2 = (float2*)(smem + KC * SROW * 4);
        if (tid < KC) sQ2[tid] = g_sq2[c0 + tid];
        __syncthreads();

        // pointer-walked inner loop: no IMAD addressing on the fma pipe
        const char* ecur = (const char*)sE;
        const char* qcur = (const char*)sQ2;
        unsigned code = (unsigned)c0;
        #pragma unroll 4
        for (int kc = 0; kc < KC; kc++) {
            const ulonglong2* ep = (const ulonglong2*)ecur;
            ull acc0 = *(const ull*)qcur;   // (sqe+8, 0)
            ull acc1 = 0ull;
            #pragma unroll
            for (int i = 0; i < 8; i++) {
                ulonglong2 e0 = ep[2 * i];
                ulonglong2 e1 = ep[2 * i + 1];
                ffma2(acc0, xr[4 * i],     e0.x);
                ffma2(acc1, xr[4 * i + 1], e0.y);
                ffma2(acc0, xr[4 * i + 2], e1.x);
                ffma2(acc1, xr[4 * i + 3], e1.y);
            }
            ull s = fadd2(acc0, acc1);
            float val = plo(s) + phi(s);   // in ~[6.5, 9.6] > 0: bits order-preserving
            unsigned key = (__float_as_uint(val) & 0xFFFFFC00u) | code;
            unsigned t = key, m;
            m = min(k0, t); t = max(k0, t); k0 = m;
            m = min(k1, t); t = max(k1, t); k1 = m;
            m = min(k2, t); t = max(k2, t); k2 = m;
            k3 = min(k3, t);
            ecur += SROW * 4;
            qcur += 8;
            code++;
        }
    }

    // ---- rescue (registers only on hot path) ----
    float s0 = __uint_as_float(k0 & 0xFFFFFC00u);
    float s1 = __uint_as_float(k1 & 0xFFFFFC00u);
    float s3 = __uint_as_float(k3 & 0xFFFFFC00u);
    int widx = (int)(k0 & 1023u);
    bool rescue = (s1 - s0 < GAP_RESCUE);
    bool full   = rescue && (s3 - s0 < CLUSTER);

    // warp-cooperative exact full scans for clustered rows (rare; cold path may spill)
    unsigned fmask = __ballot_sync(0xffffffffu, full);
    while (fmask) {
        int src = __ffs(fmask) - 1;
        fmask &= fmask - 1;
        int r = __shfl_sync(0xffffffffu, row, src);
        const float* xg = x + (size_t)r * D;
        float b0 = 3e38f, b1 = 3e38f;
        int i0 = 0, i1 = 0;
        for (int k = lane; k < K; k += 32) {
            const float* e = &g_embT[k * D];
            float dot = 0.f;
            #pragma unroll 8
            for (int d = 0; d < D; d++) dot = fmaf(xg[d], e[d], dot);
            float val = fmaf(dot, -2.f, g_sqe[k]);
            if (val < b0)      { b1 = b0; i1 = i0; b0 = val; i0 = k; }
            else if (val < b1) { b1 = val; i1 = k; }
        }
        #pragma unroll
        for (int off = 16; off; off >>= 1) {
            float ob0 = __shfl_xor_sync(0xffffffffu, b0, off);
            float ob1 = __shfl_xor_sync(0xffffffffu, b1, off);
            int   oi0 = __shfl_xor_sync(0xffffffffu, i0, off);
            int   oi1 = __shfl_xor_sync(0xffffffffu, i1, off);
            bool owin = (ob0 < b0) || (ob0 == b0 && oi0 < i0);
            if (owin) {
                float tf = b0; b0 = ob0; ob0 = tf;
                int   ti = i0; i0 = oi0; oi0 = ti;
                tf = b1; b1 = ob1; ob1 = tf;
                ti = i1; i1 = oi1; oi1 = ti;
            }
            if ((ob0 < b1) || (ob0 == b1 && oi0 < i1)) { b1 = ob0; i1 = oi0; }
        }
        if (lane == src)
            widx = (b1 - b0 < 1e-3f) ? h1_emulate_g(xg, min(i0, i1), max(i0, i1)) : i0;
    }

    if (rescue && !full) {
        // exact fp32 rescore of key top-4 using xr directly (score = sqe + sum(xr*e))
        int ids[4] = { (int)(k0 & 1023u), (int)(k1 & 1023u),
                       (int)(k2 & 1023u), (int)(k3 & 1023u) };
        #pragma unroll
        for (int a = 1; a < 4; a++) {
            int v = ids[a], b = a;
            while (b > 0 && ids[b - 1] > v) { ids[b] = ids[b - 1]; b--; }
            ids[b] = v;
        }
        float b0 = 3e38f, b1 = 3e38f;
        int i0 = 0, i1 = 0;
        #pragma unroll
        for (int j = 0; j < 4; j++) {
            const float* e = &g_embT[ids[j] * D];
            float dot = 0.f;
            #pragma unroll 8
            for (int i = 0; i < 32; i++) {
                dot = fmaf(plo(xr[i]), e[2 * i],     dot);
                dot = fmaf(phi(xr[i]), e[2 * i + 1], dot);
            }
            float val = g_sqe[ids[j]] + dot;   // xr = -2x
            if (val < b0)      { b1 = b0; i1 = i0; b0 = val; i0 = ids[j]; }
            else if (val < b1) { b1 = val; i1 = ids[j]; }
        }
        widx = (b1 - b0 < 1e-3f)
             ? h1_emulate_g(x + (size_t)row * D, min(i0, i1), max(i0, i1)) : i0;
    }

    // ---- output + loss from registers (x = -0.5 * xr, exact) ----
    const float4* qv4 = (const float4*)&g_embT[widx * D];
    float4* o4 = (float4*)(out + (size_t)row * D);
    double local = 0.0;
    #pragma unroll
    for (int i = 0; i < 16; i++) {
        float4 q = qv4[i];
        float x0 = -0.5f * plo(xr[2 * i]),     x1 = -0.5f * phi(xr[2 * i]);
        float x2 = -0.5f * plo(xr[2 * i + 1]), x3 = -0.5f * phi(xr[2 * i + 1]);
        float d0 = q.x - x0, d1 = q.y - x1, d2 = q.z - x2, d3 = q.w - x3;
        float4 o;
        o.x = x0 + d0; o.y = x1 + d1; o.z = x2 + d2; o.w = x3 + d3;
        o4[i] = o;
        local += (double)d0 * d0 + (double)d1 * d1 + (double)d2 * d2 + (double)d3 * d3;
    }
    #pragma unroll
    for (int off = 16; off > 0; off >>= 1)
        local += __shfl_down_sync(0xffffffffu, local, off);
    int w = tid >> 5;
    if (lane == 0) sred[w] = local;
    __syncthreads();
    if (tid == 0) {
        double s = 0.0;
        #pragma unroll
        for (int k = 0; k < 8; k++) s += sred[k];
        atomicAdd(&g_acc, s);
    }
}

__global__ void vq_finalize_kernel(float* __restrict__ loss_out) {
    double m = g_acc / (double)((long)NROWS * D);
    float lf = (float)m;
    *loss_out = 0.25f * lf + lf;   // BETA*commitment + codebook (equal values)
}

extern "C" void kernel_launch(void* const* d_in, const int* in_sizes, int n_in,
                              void* d_out, int out_size) {
    const float* x   = (const float*)d_in[0];   // [256,32,32,64] fp32
    const float* emb = (const float*)d_in[1];   // [64,1024] fp32
    float* out = (float*)d_out;

    cudaFuncSetAttribute(vq_mega, cudaFuncAttributeMaxDynamicSharedMemorySize, SMEM_SZ);

    vq_init_kernel<<<256, 256>>>(emb);
    vq_mega<<<NROWS / 256, 256, SMEM_SZ>>>(x, out);
    vq_finalize_kernel<<<1, 1>>>(out + (out_size - 1));
}